// round 16
// baseline (speedup 1.0000x reference)
#include <cuda_runtime.h>
#include <math.h>

#define A_COUNT 1024
#define DFEAT   128
#define NTOTAL  524288

// eps = 1e-4 / D
#define EPS (7.8125e-7f)

// rows per warp
#define RPW 8
#define HALF 4
#define BLOCK_THREADS 256
#define WARPS_PER_BLOCK (BLOCK_THREADS / 32)
#define ROWS_PER_BLOCK (WARPS_PER_BLOCK * RPW)   // 64
#define GRID_BLOCKS (NTOTAL / ROWS_PER_BLOCK)    // 8192

// Zero at module load; finalize_kernel resets it after reading, so every
// graph replay (and the first correctness call) sees zeros. No init kernel.
__device__ __align__(16) float g_per_anchor[A_COUNT];

__device__ __forceinline__ void cp_async16(void* smem_dst, const void* gsrc) {
    unsigned s = (unsigned)__cvta_generic_to_shared(smem_dst);
    asm volatile("cp.async.cg.shared.global [%0], [%1], 16;"
                 :: "r"(s), "l"(gsrc) : "memory");
}
__device__ __forceinline__ void cp_async_commit() {
    asm volatile("cp.async.commit_group;" ::: "memory");
}
template <int N>
__device__ __forceinline__ void cp_async_wait() {
    asm volatile("cp.async.wait_group %0;" :: "n"(N) : "memory");
}

__global__ __launch_bounds__(BLOCK_THREADS)
void dist_kernel(const float* __restrict__ anchors,
                 const float* __restrict__ X,
                 const int*   __restrict__ seg) {
    // 8 warps x 8 rows x 32 lanes x 16B = 32 KB -> 7 CTAs/SM.
    __shared__ float4 xs[WARPS_PER_BLOCK][RPW][32];

    const int lane = threadIdx.x & 31;
    const int warp = threadIdx.x >> 5;
    const int base = (blockIdx.x * WARPS_PER_BLOCK + warp) * RPW;

    const float4* __restrict__ X4 = reinterpret_cast<const float4*>(X);
    const float4* __restrict__ A4 = reinterpret_cast<const float4*>(anchors);

    // Stage rows as TWO commit groups of 4, so group A's compute overlaps
    // group B's in-flight loads.
    #pragma unroll
    for (int r = 0; r < HALF; r++)
        cp_async16(&xs[warp][r][lane],
                   &X4[(size_t)(base + r) * (DFEAT / 4) + lane]);
    cp_async_commit();
    #pragma unroll
    for (int r = HALF; r < RPW; r++)
        cp_async16(&xs[warp][r][lane],
                   &X4[(size_t)(base + r) * (DFEAT / 4) + lane]);
    cp_async_commit();

    // Overlap: segment ids (uniform broadcast) + first anchor row.
    int s[RPW];
    #pragma unroll
    for (int r = 0; r < RPW; r++) s[r] = seg[base + r];

    int   cur_seg = s[0];
    float4 a = A4[(size_t)cur_seg * (DFEAT / 4) + lane];

    // Phase 1a: rows 0..3 as soon as group A lands (group B still in flight).
    float ss[RPW];
    cp_async_wait<1>();
    __syncwarp();
    #pragma unroll
    for (int r = 0; r < HALF; r++) {
        if (r > 0 && s[r] != cur_seg) {
            cur_seg = s[r];
            a = A4[(size_t)cur_seg * (DFEAT / 4) + lane];
        }
        float4 x = xs[warp][r][lane];    // LDS.128, conflict-free
        float d0 = x.x - a.x;
        float d1 = x.y - a.y;
        float d2 = x.z - a.z;
        float d3 = x.w - a.w;
        ss[r] = d0 * d0 + d1 * d1 + d2 * d2 + d3 * d3;
    }

    // Phase 1b: rows 4..7 (wait should be ~free — hidden under phase 1a).
    cp_async_wait<0>();
    __syncwarp();
    #pragma unroll
    for (int r = HALF; r < RPW; r++) {
        if (s[r] != cur_seg) {
            cur_seg = s[r];
            a = A4[(size_t)cur_seg * (DFEAT / 4) + lane];
        }
        float4 x = xs[warp][r][lane];
        float d0 = x.x - a.x;
        float d1 = x.y - a.y;
        float d2 = x.z - a.z;
        float d3 = x.w - a.w;
        ss[r] = d0 * d0 + d1 * d1 + d2 * d2 + d3 * d3;
    }

    // Phase 2: fold-reduce — map 8 row-sums onto lane groups.
    // After 3 folds + 2 butterflies, lanes 4r..4r+3 hold the full sum of
    // row r. 9 shuffles total instead of 40.
    const bool b16 = lane & 16, b8 = lane & 8, b4 = lane & 4;
    float t[4];
    #pragma unroll
    for (int r = 0; r < 4; r++) {
        float snd = b16 ? ss[r] : ss[r + 4];
        float kp  = b16 ? ss[r + 4] : ss[r];
        t[r] = kp + __shfl_xor_sync(0xffffffffu, snd, 16);
    }
    float t2[2];
    #pragma unroll
    for (int r = 0; r < 2; r++) {
        float snd = b8 ? t[r] : t[r + 2];
        float kp  = b8 ? t[r + 2] : t[r];
        t2[r] = kp + __shfl_xor_sync(0xffffffffu, snd, 8);
    }
    {
        float snd = b4 ? t2[0] : t2[1];
        float kp  = b4 ? t2[1] : t2[0];
        t2[0] = kp + __shfl_xor_sync(0xffffffffu, snd, 4);
    }
    t2[0] += __shfl_xor_sync(0xffffffffu, t2[0], 2);
    t2[0] += __shfl_xor_sync(0xffffffffu, t2[0], 1);

    // Parallel sqrt on every lane (one MUFU latency, not 8 serial).
    float d = sqrtf(t2[0] + EPS);

    // Gather the 8 row distances (lane 4r holds row r) — pipelined shuffles.
    float dr[RPW];
    #pragma unroll
    for (int r = 0; r < RPW; r++)
        dr[r] = __shfl_sync(0xffffffffu, d, 4 * r);

    // Phase 3: lane 0 segment walk (adds only; sqrt already done).
    if (lane == 0) {
        float acc = 0.0f;
        int aseg = s[0];
        #pragma unroll
        for (int r = 0; r < RPW; r++) {
            if (s[r] != aseg) {
                atomicAdd(&g_per_anchor[aseg], acc);
                acc = 0.0f;
                aseg = s[r];
            }
            acc += dr[r];
        }
        atomicAdd(&g_per_anchor[aseg], acc);
    }
}

// Lean finalize: 256 threads, one float4 (4 anchors) per thread, one barrier.
__global__ __launch_bounds__(256)
void finalize_kernel(float* __restrict__ out) {
    __shared__ float sdata[8];
    const int tid  = threadIdx.x;
    const int lane = tid & 31;
    const int warp = tid >> 5;

    float4* pa4 = reinterpret_cast<float4*>(g_per_anchor);
    float4 p = pa4[tid];                       // LDG.128, 256 in flight
    pa4[tid] = make_float4(0.f, 0.f, 0.f, 0.f);  // reset for next replay

    float v = log1pf(p.x) + log1pf(p.y) + log1pf(p.z) + log1pf(p.w);

    #pragma unroll
    for (int off = 16; off; off >>= 1)
        v += __shfl_xor_sync(0xffffffffu, v, off);
    if (lane == 0) sdata[warp] = v;
    __syncthreads();

    if (tid == 0) {
        float w = 0.0f;
        #pragma unroll
        for (int i = 0; i < 8; i++) w += sdata[i];
        out[0] = w / (float)NTOTAL;
    }
}

extern "C" void kernel_launch(void* const* d_in, const int* in_sizes, int n_in,
                              void* d_out, int out_size) {
    const float* anchors = (const float*)d_in[0];   // [A, D]
    const float* Xn_flat = (const float*)d_in[1];   // [TOTAL, D]
    const int*   seg     = (const int*)d_in[2];     // [TOTAL]
    float* out = (float*)d_out;

    dist_kernel<<<GRID_BLOCKS, BLOCK_THREADS>>>(anchors, Xn_flat, seg);

    finalize_kernel<<<1, 256>>>(out);
}

// round 17
// speedup vs baseline: 1.0007x; 1.0007x over previous
#include <cuda_runtime.h>
#include <math.h>

#define A_COUNT 1024
#define DFEAT   128
#define NTOTAL  524288

// eps = 1e-4 / D
#define EPS (7.8125e-7f)

// rows per warp
#define RPW 8
#define BLOCK_THREADS 256
#define WARPS_PER_BLOCK (BLOCK_THREADS / 32)
#define ROWS_PER_BLOCK (WARPS_PER_BLOCK * RPW)   // 64
#define GRID_BLOCKS (NTOTAL / ROWS_PER_BLOCK)    // 8192
#define TILE_BYTES (ROWS_PER_BLOCK * DFEAT * 4)  // 32768

// Zero at module load; finalize_kernel resets it after reading, so every
// graph replay (and the first correctness call) sees zeros. No init kernel.
__device__ __align__(16) float g_per_anchor[A_COUNT];

__global__ __launch_bounds__(BLOCK_THREADS)
void dist_kernel(const float* __restrict__ anchors,
                 const float* __restrict__ X,
                 const int*   __restrict__ seg) {
    // One contiguous 32KB tile: rows 64*bid .. 64*bid+63 of X.
    __shared__ __align__(128) float4 tile[ROWS_PER_BLOCK][DFEAT / 4];
    __shared__ __align__(8) unsigned long long mbar;

    const int lane = threadIdx.x & 31;
    const int warp = threadIdx.x >> 5;
    const int base = (blockIdx.x * WARPS_PER_BLOCK + warp) * RPW;

    const float4* __restrict__ A4 = reinterpret_cast<const float4*>(anchors);

    // --- single bulk copy: gmem -> smem, 32KB, TMA bulk path (UBLKCP) ---
    unsigned mb = (unsigned)__cvta_generic_to_shared(&mbar);
    unsigned td = (unsigned)__cvta_generic_to_shared(&tile[0][0]);
    if (threadIdx.x == 0) {
        asm volatile("mbarrier.init.shared.b64 [%0], %1;"
                     :: "r"(mb), "r"(1) : "memory");
    }
    __syncthreads();
    if (threadIdx.x == 0) {
        asm volatile("mbarrier.arrive.expect_tx.shared.b64 _, [%0], %1;"
                     :: "r"(mb), "r"(TILE_BYTES) : "memory");
        const char* src = reinterpret_cast<const char*>(X)
                        + (size_t)blockIdx.x * TILE_BYTES;
        asm volatile("cp.async.bulk.shared::cta.global.mbarrier::complete_tx::bytes "
                     "[%0], [%1], %2, [%3];"
                     :: "r"(td), "l"(src), "r"(TILE_BYTES), "r"(mb) : "memory");
    }

    // Overlap with the copy: segment ids (uniform broadcast) + first anchor.
    int s[RPW];
    #pragma unroll
    for (int r = 0; r < RPW; r++) s[r] = seg[base + r];

    int   cur_seg = s[0];
    float4 a = A4[(size_t)cur_seg * (DFEAT / 4) + lane];

    // Wait for the bulk copy (phase 0).
    {
        unsigned done;
        asm volatile(
            "{\n\t.reg .pred p;\n\t"
            "mbarrier.try_wait.parity.shared.b64 p, [%1], %2;\n\t"
            "selp.b32 %0, 1, 0, p;\n\t}"
            : "=r"(done) : "r"(mb), "r"(0) : "memory");
        while (!done) {
            asm volatile(
                "{\n\t.reg .pred p;\n\t"
                "mbarrier.try_wait.parity.shared.b64 p, [%1], %2;\n\t"
                "selp.b32 %0, 1, 0, p;\n\t}"
                : "=r"(done) : "r"(mb), "r"(0) : "memory");
        }
    }
    __syncwarp();

    // Phase 1: all 8 per-lane partials (independent LDS+FMA chains).
    float ss[RPW];
    #pragma unroll
    for (int r = 0; r < RPW; r++) {
        if (r > 0 && s[r] != cur_seg) {
            // Anchor change (warp-uniform, rare): reload for remaining rows.
            cur_seg = s[r];
            a = A4[(size_t)cur_seg * (DFEAT / 4) + lane];
        }
        float4 x = tile[warp * RPW + r][lane];   // LDS.128, conflict-free
        float d0 = x.x - a.x;
        float d1 = x.y - a.y;
        float d2 = x.z - a.z;
        float d3 = x.w - a.w;
        ss[r] = d0 * d0 + d1 * d1 + d2 * d2 + d3 * d3;
    }

    // Phase 2: fold-reduce — map 8 row-sums onto lane groups.
    // After 3 folds + 2 butterflies, lanes 4r..4r+3 hold the full sum of
    // row r. 9 shuffles total instead of 40.
    const bool b16 = lane & 16, b8 = lane & 8, b4 = lane & 4;
    float t[4];
    #pragma unroll
    for (int r = 0; r < 4; r++) {
        float snd = b16 ? ss[r] : ss[r + 4];
        float kp  = b16 ? ss[r + 4] : ss[r];
        t[r] = kp + __shfl_xor_sync(0xffffffffu, snd, 16);
    }
    float t2[2];
    #pragma unroll
    for (int r = 0; r < 2; r++) {
        float snd = b8 ? t[r] : t[r + 2];
        float kp  = b8 ? t[r + 2] : t[r];
        t2[r] = kp + __shfl_xor_sync(0xffffffffu, snd, 8);
    }
    {
        float snd = b4 ? t2[0] : t2[1];
        float kp  = b4 ? t2[1] : t2[0];
        t2[0] = kp + __shfl_xor_sync(0xffffffffu, snd, 4);
    }
    t2[0] += __shfl_xor_sync(0xffffffffu, t2[0], 2);
    t2[0] += __shfl_xor_sync(0xffffffffu, t2[0], 1);

    // Parallel sqrt on every lane (one MUFU latency, not 8 serial).
    float d = sqrtf(t2[0] + EPS);

    // Gather the 8 row distances (lane 4r holds row r) — pipelined shuffles.
    float dr[RPW];
    #pragma unroll
    for (int r = 0; r < RPW; r++)
        dr[r] = __shfl_sync(0xffffffffu, d, 4 * r);

    // Phase 3: lane 0 segment walk (adds only; sqrt already done).
    if (lane == 0) {
        float acc = 0.0f;
        int aseg = s[0];
        #pragma unroll
        for (int r = 0; r < RPW; r++) {
            if (s[r] != aseg) {
                atomicAdd(&g_per_anchor[aseg], acc);
                acc = 0.0f;
                aseg = s[r];
            }
            acc += dr[r];
        }
        atomicAdd(&g_per_anchor[aseg], acc);
    }
}

// Lean finalize: 256 threads, one float4 (4 anchors) per thread, one barrier.
__global__ __launch_bounds__(256)
void finalize_kernel(float* __restrict__ out) {
    __shared__ float sdata[8];
    const int tid  = threadIdx.x;
    const int lane = tid & 31;
    const int warp = tid >> 5;

    float4* pa4 = reinterpret_cast<float4*>(g_per_anchor);
    float4 p = pa4[tid];                       // LDG.128, 256 in flight
    pa4[tid] = make_float4(0.f, 0.f, 0.f, 0.f);  // reset for next replay

    float v = log1pf(p.x) + log1pf(p.y) + log1pf(p.z) + log1pf(p.w);

    #pragma unroll
    for (int off = 16; off; off >>= 1)
        v += __shfl_xor_sync(0xffffffffu, v, off);
    if (lane == 0) sdata[warp] = v;
    __syncthreads();

    if (tid == 0) {
        float w = 0.0f;
        #pragma unroll
        for (int i = 0; i < 8; i++) w += sdata[i];
        out[0] = w / (float)NTOTAL;
    }
}

extern "C" void kernel_launch(void* const* d_in, const int* in_sizes, int n_in,
                              void* d_out, int out_size) {
    const float* anchors = (const float*)d_in[0];   // [A, D]
    const float* Xn_flat = (const float*)d_in[1];   // [TOTAL, D]
    const int*   seg     = (const int*)d_in[2];     // [TOTAL]
    float* out = (float*)d_out;

    dist_kernel<<<GRID_BLOCKS, BLOCK_THREADS>>>(anchors, Xn_flat, seg);

    finalize_kernel<<<1, 256>>>(out);
}